// round 5
// baseline (speedup 1.0000x reference)
#include <cuda_runtime.h>
#include <cstdint>

#define NV    64
#define TMAX  2048
#define EDIM  512
#define HDIM  64
#define G3    192   // 3*H

// ---------------- scratch ----------------
__device__ float g_xg[(size_t)NV * TMAX * G3];   // [V][T][192] x_gates (+b_ih)
__device__ float g_hT[NV * HDIM];
__device__ float g_Wt[EDIM * G3];                // W_ih transposed: [e][n]
__device__ float g_hid[64];                      // MLP hidden

// ---------------- helpers ----------------
typedef unsigned long long ull;
__device__ __forceinline__ void ffma2(ull &d, ull a, ull b) {
    asm volatile("fma.rn.f32x2 %0, %1, %2, %0;" : "+l"(d) : "l"(a), "l"(b));
}
__device__ __forceinline__ float hsum2(ull d) {
    unsigned int a, b;
    asm("mov.b64 {%0, %1}, %2;" : "=r"(a), "=r"(b) : "l"(d));
    return __uint_as_float(a) + __uint_as_float(b);
}
__device__ __forceinline__ void unpack2(ull d, float &x, float &y) {
    unsigned int a, b;
    asm("mov.b64 {%0, %1}, %2;" : "=r"(a), "=r"(b) : "l"(d));
    x = __uint_as_float(a); y = __uint_as_float(b);
}
__device__ __forceinline__ void cp_async16(void* dst, const void* src) {
    unsigned int d = (unsigned int)__cvta_generic_to_shared(dst);
    asm volatile("cp.async.ca.shared.global [%0], [%1], 16;" :: "r"(d), "l"(src));
}

// =====================================================================
// Kernel 0: transpose W_ih [192,512] -> g_Wt [512,192]
// =====================================================================
__global__ __launch_bounds__(256) void transpose_wih(const float* __restrict__ W_ih)
{
    int idx = blockIdx.x * 256 + threadIdx.x;
    if (idx < EDIM * G3) {
        int e = idx / G3, n = idx - e * G3;
        g_Wt[idx] = W_ih[(size_t)n * EDIM + e];
    }
}

// =====================================================================
// Kernel 1: x_gates GEMM, DOUBLE-BUFFERED.
// Block 64(M) x 192(N) x 32(K), 128 threads, 8x12 f32x2 microtile.
// Stage i+1 loads (cp.async B + STS A) overlap stage i compute;
// wait+barrier sits AFTER compute. Dynamic smem (80KB), 2 CTAs/SM.
// =====================================================================
extern __shared__ __align__(16) char g_dynsmem[];

__global__ __launch_bounds__(128, 2) void gemm_kernel(
    const float* __restrict__ emb, const int* __restrict__ lengths,
    const float* __restrict__ b_ih)
{
    const int v  = blockIdx.y;
    const int tt = blockIdx.x;
    if (tt * 64 >= lengths[v]) return;

    // layout: Asd[2][32][64] float2 (32KB) then Bs[2][32][192] float (48KB)
    float2 (*Asd)[32][64] = (float2 (*)[32][64])g_dynsmem;
    float  (*Bs)[32][192] = (float (*)[32][192])(g_dynsmem + 2 * 32 * 64 * sizeof(float2));

    const int tid = threadIdx.x;
    const int tm = tid >> 4;        // 0..7  -> rows tm*8 .. +7
    const int tn = tid & 15;        // 0..15 -> cols tn*12 .. +11
    const int ar = tid >> 1;        // 0..63 A row for loading
    const int aq = tid & 1;         // k-half (16 floats)
    const int kb = tid >> 2;        // 0..31 B row (k)
    const int seg = tid & 3;        // 48-float segment

    const float* Ag = emb + ((size_t)v * TMAX + (size_t)tt * 64 + ar) * EDIM + aq * 16;
    const float* Bg = g_Wt + (size_t)kb * G3 + seg * 48;

    ull acc[8][6];
#pragma unroll
    for (int i = 0; i < 8; i++)
#pragma unroll
        for (int j = 0; j < 6; j++) acc[i][j] = 0ull;

    float4 aR[4];
    // ---- prologue: stage 0 ----
#pragma unroll
    for (int i = 0; i < 4; i++) aR[i] = *(const float4*)(Ag + i * 4);
#pragma unroll
    for (int i = 0; i < 12; i++)
        cp_async16(&Bs[0][kb][seg * 48 + i * 4], Bg + i * 4);
    asm volatile("cp.async.commit_group;" ::: "memory");
#pragma unroll
    for (int i = 0; i < 4; i++) {
        Asd[0][aq * 16 + i * 4 + 0][ar] = make_float2(aR[i].x, aR[i].x);
        Asd[0][aq * 16 + i * 4 + 1][ar] = make_float2(aR[i].y, aR[i].y);
        Asd[0][aq * 16 + i * 4 + 2][ar] = make_float2(aR[i].z, aR[i].z);
        Asd[0][aq * 16 + i * 4 + 3][ar] = make_float2(aR[i].w, aR[i].w);
    }
    // prefetch A stage 1 into regs
#pragma unroll
    for (int i = 0; i < 4; i++) aR[i] = *(const float4*)(Ag + 32 + i * 4);
    asm volatile("cp.async.wait_group 0;" ::: "memory");
    __syncthreads();

    for (int it = 0; it < 16; it++) {
        const int cur = it & 1, nxt = cur ^ 1;
        if (it < 15) {
            // launch next-stage loads: overlap with this stage's compute
            const float* bsrc = Bg + (size_t)(it + 1) * 32 * G3;
#pragma unroll
            for (int i = 0; i < 12; i++)
                cp_async16(&Bs[nxt][kb][seg * 48 + i * 4], bsrc + i * 4);
            asm volatile("cp.async.commit_group;" ::: "memory");
#pragma unroll
            for (int i = 0; i < 4; i++) {
                Asd[nxt][aq * 16 + i * 4 + 0][ar] = make_float2(aR[i].x, aR[i].x);
                Asd[nxt][aq * 16 + i * 4 + 1][ar] = make_float2(aR[i].y, aR[i].y);
                Asd[nxt][aq * 16 + i * 4 + 2][ar] = make_float2(aR[i].z, aR[i].z);
                Asd[nxt][aq * 16 + i * 4 + 3][ar] = make_float2(aR[i].w, aR[i].w);
            }
            if (it < 14) {
#pragma unroll
                for (int i = 0; i < 4; i++)
                    aR[i] = *(const float4*)(Ag + (it + 2) * 32 + i * 4);
            }
        }
        // compute current stage (fma-bound, ~3k cycles — hides the loads above)
#pragma unroll 4
        for (int kk = 0; kk < 32; kk++) {
            ull a8[8];
            const ull* ap = (const ull*)&Asd[cur][kk][tm * 8];
#pragma unroll
            for (int i = 0; i < 8; i++) a8[i] = ap[i];
            ull b6[6];
            const ull* bp = (const ull*)&Bs[cur][kk][tn * 12];
#pragma unroll
            for (int j = 0; j < 6; j++) b6[j] = bp[j];
#pragma unroll
            for (int i = 0; i < 8; i++)
#pragma unroll
                for (int j = 0; j < 6; j++) ffma2(acc[i][j], a8[i], b6[j]);
        }
        if (it < 15) {
            asm volatile("cp.async.wait_group 0;" ::: "memory");
            __syncthreads();
        }
    }

    // epilogue: +bias, store
    float bias[12];
    *(float4*)&bias[0] = *(const float4*)(b_ih + tn * 12 + 0);
    *(float4*)&bias[4] = *(const float4*)(b_ih + tn * 12 + 4);
    *(float4*)&bias[8] = *(const float4*)(b_ih + tn * 12 + 8);
#pragma unroll
    for (int i = 0; i < 8; i++) {
        size_t row = (size_t)v * TMAX + (size_t)tt * 64 + tm * 8 + i;
        float* outp = g_xg + row * G3 + tn * 12;
        float o[12];
#pragma unroll
        for (int j = 0; j < 6; j++) {
            float x, y; unpack2(acc[i][j], x, y);
            o[2 * j]     = x + bias[2 * j];
            o[2 * j + 1] = y + bias[2 * j + 1];
        }
        *(float4*)(outp + 0) = make_float4(o[0], o[1], o[2], o[3]);
        *(float4*)(outp + 4) = make_float4(o[4], o[5], o[6], o[7]);
        *(float4*)(outp + 8) = make_float4(o[8], o[9], o[10], o[11]);
    }
}

// =====================================================================
// Kernel 2: GRU scan. 128 threads = (j 0..63) x (half 0..1).
// xg now prefetched per-thread via 3-deep REGISTER LDG pipeline (no smem
// ring, no cp.async): each thread's 3 xg values are private.
// Per-gate blocks ordered so shfl/MUFU latency hides under next gate's fma.
// =====================================================================
__global__ __launch_bounds__(128) void scan_kernel(
    const int* __restrict__ lengths, const float* __restrict__ W_hh,
    const float* __restrict__ b_hh)
{
    const int v   = blockIdx.x;
    const int len = lengths[v];
    const int tid = threadIdx.x;
    const int j    = tid >> 1;
    const int half = tid & 1;

    __shared__ __align__(16) float sh_h[2][HDIM];

    // W_hh rows j, 64+j, 128+j (k-half slice) as f32x2 pairs
    ull wr[16], wz[16], wn[16];
    {
        const ull* pr = (const ull*)(W_hh + (size_t)(j)       * HDIM + half * 32);
        const ull* pz = (const ull*)(W_hh + (size_t)(64 + j)  * HDIM + half * 32);
        const ull* pn = (const ull*)(W_hh + (size_t)(128 + j) * HDIM + half * 32);
#pragma unroll
        for (int i = 0; i < 16; i++) { wr[i] = pr[i]; wz[i] = pz[i]; wn[i] = pn[i]; }
    }
    const float br = b_hh[j], bz = b_hh[64 + j], bn = b_hh[128 + j];
    float myh = 0.f;
    if (tid < HDIM) sh_h[0][tid] = 0.f;

    const float* xr_p = g_xg + (size_t)v * TMAX * G3 + j;
    const float* xz_p = xr_p + 64;
    const float* xn_p = xr_p + 128;

    // 3-deep register prefetch: slots for t, t+1, t+2
    float xrA, xzA, xnA, xrB, xzB, xnB, xrC, xzC, xnC;
    xrA = xr_p[0];           xzA = xz_p[0];           xnA = xn_p[0];
    xrB = xr_p[G3];          xzB = xz_p[G3];          xnB = xn_p[G3];
    xrC = xr_p[2 * G3];      xzC = xz_p[2 * G3];      xnC = xn_p[2 * G3];
    __syncthreads();

    for (int t = 0; t < len; t++) {
        // ---- matvec over this thread's k-half, gate-by-gate ----
        const ull* hp = (const ull*)(&sh_h[t & 1][half * 32]);
        ull h8[16];
#pragma unroll
        for (int i = 0; i < 16; i++) h8[i] = hp[i];

        ull a0 = 0ull, a1 = 0ull;
#pragma unroll
        for (int i = 0; i < 16; i += 2) { ffma2(a0, wr[i], h8[i]); ffma2(a1, wr[i + 1], h8[i + 1]); }
        float sr = hsum2(a0) + hsum2(a1);
        sr += __shfl_xor_sync(0xffffffffu, sr, 1);   // issues early; z-fma hides it

        ull c0 = 0ull, c1 = 0ull;
#pragma unroll
        for (int i = 0; i < 16; i += 2) { ffma2(c0, wz[i], h8[i]); ffma2(c1, wz[i + 1], h8[i + 1]); }
        float sz = hsum2(c0) + hsum2(c1);
        sz += __shfl_xor_sync(0xffffffffu, sz, 1);

        float rr = __fdividef(1.f, 1.f + __expf(-(xrA + sr + br)));  // MUFU hides under n-fma

        ull e0 = 0ull, e1 = 0ull;
#pragma unroll
        for (int i = 0; i < 16; i += 2) { ffma2(e0, wn[i], h8[i]); ffma2(e1, wn[i + 1], h8[i + 1]); }
        float sn = hsum2(e0) + hsum2(e1);
        sn += __shfl_xor_sync(0xffffffffu, sn, 1);

        float zz = __fdividef(1.f, 1.f + __expf(-(xzA + sz + bz)));
        float pre = xnA + rr * (sn + bn);
        float nn = 1.f - __fdividef(2.f, 1.f + __expf(2.f * pre));   // tanh(pre)
        myh = nn + zz * (myh - nn);
        if (half == 0) sh_h[(t + 1) & 1][j] = myh;

        // rotate prefetch regs; issue loads for t+3 (consumed 3 steps later)
        xrA = xrB; xzA = xzB; xnA = xnB;
        xrB = xrC; xzB = xzC; xnB = xnC;
        {
            int src = t + 3; if (src > TMAX - 1) src = TMAX - 1;
            size_t off = (size_t)src * G3;
            xrC = xr_p[off]; xzC = xz_p[off]; xnC = xn_p[off];
        }
        __syncthreads();
    }

    if (half == 0) g_hT[v * HDIM + j] = myh;
}

// =====================================================================
// Kernel 3a: MLP layer 1 — 64 blocks, one hidden unit each.
// =====================================================================
__global__ __launch_bounds__(128) void mlp1_kernel(
    const float* __restrict__ W1, const float* __restrict__ b1)
{
    const int i = blockIdx.x;
    const int tid = threadIdx.x;
    const int warp = tid >> 5, lane = tid & 31;
    __shared__ float red[4];

    const float* wrow = W1 + (size_t)i * (NV * HDIM);
    float s = 0.f;
#pragma unroll
    for (int it = 0; it < 8; it++) {
        int k = (it * 128 + tid) * 4;
        float4 wv = *(const float4*)(wrow + k);
        float4 hv = *(const float4*)(g_hT + k);
        s += wv.x * hv.x + wv.y * hv.y + wv.z * hv.z + wv.w * hv.w;
    }
#pragma unroll
    for (int off = 16; off; off >>= 1) s += __shfl_xor_sync(0xffffffffu, s, off);
    if (lane == 0) red[warp] = s;
    __syncthreads();
    if (tid == 0)
        g_hid[i] = fmaxf(red[0] + red[1] + red[2] + red[3] + b1[i], 0.f);
}

// =====================================================================
// Kernel 3b: MLP layer 2 — one warp.
// =====================================================================
__global__ __launch_bounds__(32) void mlp2_kernel(
    const float* __restrict__ W2, const float* __restrict__ b2,
    float* __restrict__ out)
{
    const int lane = threadIdx.x;
    float s = g_hid[lane] * W2[lane] + g_hid[lane + 32] * W2[lane + 32];
#pragma unroll
    for (int off = 16; off; off >>= 1) s += __shfl_xor_sync(0xffffffffu, s, off);
    if (lane == 0) out[0] = s + b2[0];
}

// =====================================================================
extern "C" void kernel_launch(void* const* d_in, const int* in_sizes, int n_in,
                              void* d_out, int out_size)
{
    const float* emb     = (const float*)d_in[0];
    const int*   lengths = (const int*)  d_in[1];
    const float* W_ih    = (const float*)d_in[2];
    const float* W_hh    = (const float*)d_in[3];
    const float* b_ih    = (const float*)d_in[4];
    const float* b_hh    = (const float*)d_in[5];
    const float* W1      = (const float*)d_in[6];
    const float* b1      = (const float*)d_in[7];
    const float* W2      = (const float*)d_in[8];
    const float* b2      = (const float*)d_in[9];

    static int smem_set = 0;
    const int GEMM_SMEM = 2 * 32 * 64 * (int)sizeof(float2) + 2 * 32 * 192 * (int)sizeof(float);
    if (!smem_set) {
        cudaFuncSetAttribute(gemm_kernel, cudaFuncAttributeMaxDynamicSharedMemorySize, GEMM_SMEM);
        smem_set = 1;
    }

    transpose_wih<<<(EDIM * G3 + 255) / 256, 256>>>(W_ih);
    dim3 ggrid(TMAX / 64, NV);
    gemm_kernel<<<ggrid, 128, GEMM_SMEM>>>(emb, lengths, b_ih);
    scan_kernel<<<NV, 128>>>(lengths, W_hh, b_hh);
    mlp1_kernel<<<64, 128>>>(W1, b1);
    mlp2_kernel<<<1, 32>>>(W2, b2, (float*)d_out);
}

// round 7
// speedup vs baseline: 1.6243x; 1.6243x over previous
#include <cuda_runtime.h>
#include <cstdint>

#define NV    64
#define TMAX  2048
#define EDIM  512
#define HDIM  64
#define G3    192   // 3*H

// ---------------- scratch ----------------
__device__ float g_xg[(size_t)NV * TMAX * G3];   // [V][T][192] x_gates (+b_ih)
__device__ float g_hT[NV * HDIM];
__device__ float g_Wt[EDIM * G3];                // W_ih transposed: [e][n]
__device__ float g_hid[64];                      // MLP hidden

// ---------------- helpers ----------------
typedef unsigned long long ull;
__device__ __forceinline__ void ffma2(ull &d, ull a, ull b) {
    asm volatile("fma.rn.f32x2 %0, %1, %2, %0;" : "+l"(d) : "l"(a), "l"(b));
}
__device__ __forceinline__ float hsum2(ull d) {
    unsigned int a, b;
    asm("mov.b64 {%0, %1}, %2;" : "=r"(a), "=r"(b) : "l"(d));
    return __uint_as_float(a) + __uint_as_float(b);
}
__device__ __forceinline__ void unpack2(ull d, float &x, float &y) {
    unsigned int a, b;
    asm("mov.b64 {%0, %1}, %2;" : "=r"(a), "=r"(b) : "l"(d));
    x = __uint_as_float(a); y = __uint_as_float(b);
}
__device__ __forceinline__ void cp_async16(void* dst, const void* src) {
    unsigned int d = (unsigned int)__cvta_generic_to_shared(dst);
    asm volatile("cp.async.ca.shared.global [%0], [%1], 16;" :: "r"(d), "l"(src));
}
__device__ __forceinline__ float tanh_fast(float x) {
    float y;
    asm("tanh.approx.f32 %0, %1;" : "=f"(y) : "f"(x));
    return y;
}
__device__ __forceinline__ float sigmoid_fast(float x) {
    return fmaf(0.5f, tanh_fast(0.5f * x), 0.5f);
}

// =====================================================================
// Kernel 0: transpose W_ih [192,512] -> g_Wt [512,192]
// =====================================================================
__global__ __launch_bounds__(256) void transpose_wih(const float* __restrict__ W_ih)
{
    int idx = blockIdx.x * 256 + threadIdx.x;
    if (idx < EDIM * G3) {
        int e = idx / G3, n = idx - e * G3;
        g_Wt[idx] = W_ih[(size_t)n * EDIM + e];
    }
}

// =====================================================================
// Kernel 1: x_gates GEMM, double-buffered (unchanged from round 5).
// Block 64(M) x 192(N) x 32(K), 128 threads, 8x12 f32x2 microtile.
// =====================================================================
extern __shared__ __align__(16) char g_dynsmem[];

__global__ __launch_bounds__(128, 2) void gemm_kernel(
    const float* __restrict__ emb, const int* __restrict__ lengths,
    const float* __restrict__ b_ih)
{
    const int v  = blockIdx.y;
    const int tt = blockIdx.x;
    if (tt * 64 >= lengths[v]) return;

    float2 (*Asd)[32][64] = (float2 (*)[32][64])g_dynsmem;
    float  (*Bs)[32][192] = (float (*)[32][192])(g_dynsmem + 2 * 32 * 64 * sizeof(float2));

    const int tid = threadIdx.x;
    const int tm = tid >> 4;
    const int tn = tid & 15;
    const int ar = tid >> 1;
    const int aq = tid & 1;
    const int kb = tid >> 2;
    const int seg = tid & 3;

    const float* Ag = emb + ((size_t)v * TMAX + (size_t)tt * 64 + ar) * EDIM + aq * 16;
    const float* Bg = g_Wt + (size_t)kb * G3 + seg * 48;

    ull acc[8][6];
#pragma unroll
    for (int i = 0; i < 8; i++)
#pragma unroll
        for (int j = 0; j < 6; j++) acc[i][j] = 0ull;

    float4 aR[4];
#pragma unroll
    for (int i = 0; i < 4; i++) aR[i] = *(const float4*)(Ag + i * 4);
#pragma unroll
    for (int i = 0; i < 12; i++)
        cp_async16(&Bs[0][kb][seg * 48 + i * 4], Bg + i * 4);
    asm volatile("cp.async.commit_group;" ::: "memory");
#pragma unroll
    for (int i = 0; i < 4; i++) {
        Asd[0][aq * 16 + i * 4 + 0][ar] = make_float2(aR[i].x, aR[i].x);
        Asd[0][aq * 16 + i * 4 + 1][ar] = make_float2(aR[i].y, aR[i].y);
        Asd[0][aq * 16 + i * 4 + 2][ar] = make_float2(aR[i].z, aR[i].z);
        Asd[0][aq * 16 + i * 4 + 3][ar] = make_float2(aR[i].w, aR[i].w);
    }
#pragma unroll
    for (int i = 0; i < 4; i++) aR[i] = *(const float4*)(Ag + 32 + i * 4);
    asm volatile("cp.async.wait_group 0;" ::: "memory");
    __syncthreads();

    for (int it = 0; it < 16; it++) {
        const int cur = it & 1, nxt = cur ^ 1;
        if (it < 15) {
            const float* bsrc = Bg + (size_t)(it + 1) * 32 * G3;
#pragma unroll
            for (int i = 0; i < 12; i++)
                cp_async16(&Bs[nxt][kb][seg * 48 + i * 4], bsrc + i * 4);
            asm volatile("cp.async.commit_group;" ::: "memory");
#pragma unroll
            for (int i = 0; i < 4; i++) {
                Asd[nxt][aq * 16 + i * 4 + 0][ar] = make_float2(aR[i].x, aR[i].x);
                Asd[nxt][aq * 16 + i * 4 + 1][ar] = make_float2(aR[i].y, aR[i].y);
                Asd[nxt][aq * 16 + i * 4 + 2][ar] = make_float2(aR[i].z, aR[i].z);
                Asd[nxt][aq * 16 + i * 4 + 3][ar] = make_float2(aR[i].w, aR[i].w);
            }
            if (it < 14) {
#pragma unroll
                for (int i = 0; i < 4; i++)
                    aR[i] = *(const float4*)(Ag + (it + 2) * 32 + i * 4);
            }
        }
#pragma unroll 4
        for (int kk = 0; kk < 32; kk++) {
            ull a8[8];
            const ull* ap = (const ull*)&Asd[cur][kk][tm * 8];
#pragma unroll
            for (int i = 0; i < 8; i++) a8[i] = ap[i];
            ull b6[6];
            const ull* bp = (const ull*)&Bs[cur][kk][tn * 12];
#pragma unroll
            for (int j = 0; j < 6; j++) b6[j] = bp[j];
#pragma unroll
            for (int i = 0; i < 8; i++)
#pragma unroll
                for (int j = 0; j < 6; j++) ffma2(acc[i][j], a8[i], b6[j]);
        }
        if (it < 15) {
            asm volatile("cp.async.wait_group 0;" ::: "memory");
            __syncthreads();
        }
    }

    float bias[12];
    *(float4*)&bias[0] = *(const float4*)(b_ih + tn * 12 + 0);
    *(float4*)&bias[4] = *(const float4*)(b_ih + tn * 12 + 4);
    *(float4*)&bias[8] = *(const float4*)(b_ih + tn * 12 + 8);
#pragma unroll
    for (int i = 0; i < 8; i++) {
        size_t row = (size_t)v * TMAX + (size_t)tt * 64 + tm * 8 + i;
        float* outp = g_xg + row * G3 + tn * 12;
        float o[12];
#pragma unroll
        for (int j = 0; j < 6; j++) {
            float x, y; unpack2(acc[i][j], x, y);
            o[2 * j]     = x + bias[2 * j];
            o[2 * j + 1] = y + bias[2 * j + 1];
        }
        *(float4*)(outp + 0) = make_float4(o[0], o[1], o[2], o[3]);
        *(float4*)(outp + 4) = make_float4(o[4], o[5], o[6], o[7]);
        *(float4*)(outp + 8) = make_float4(o[8], o[9], o[10], o[11]);
    }
}

// =====================================================================
// Kernel 2: GRU scan. 128 threads = (j 0..63) x (half 0..1).
// cp.async smem ring (round-4 proven: per-thread wait THEN barrier),
// 16B copies from 48 threads, MUFU.TANH activations.
// =====================================================================
__global__ __launch_bounds__(128) void scan_kernel(
    const int* __restrict__ lengths, const float* __restrict__ W_hh,
    const float* __restrict__ b_hh)
{
    const int v   = blockIdx.x;
    const int len = lengths[v];
    const int tid = threadIdx.x;
    const int j    = tid >> 1;
    const int half = tid & 1;

    __shared__ __align__(16) float sh_h[2][HDIM];
    __shared__ __align__(16) float sh_xg[4][G3];

    ull wr[16], wz[16], wn[16];
    {
        const ull* pr = (const ull*)(W_hh + (size_t)(j)       * HDIM + half * 32);
        const ull* pz = (const ull*)(W_hh + (size_t)(64 + j)  * HDIM + half * 32);
        const ull* pn = (const ull*)(W_hh + (size_t)(128 + j) * HDIM + half * 32);
#pragma unroll
        for (int i = 0; i < 16; i++) { wr[i] = pr[i]; wz[i] = pz[i]; wn[i] = pn[i]; }
    }
    const float br = b_hh[j], bz = b_hh[64 + j], bn = b_hh[128 + j];
    float myh = 0.f;
    if (tid < HDIM) sh_h[0][tid] = 0.f;

    const float* xgbase = g_xg + (size_t)v * TMAX * G3;

    // prefill 3 buffers (data 0,1,2), one commit group each
#pragma unroll
    for (int i = 0; i < 3; i++) {
        if (tid < 48)
            cp_async16(&sh_xg[i][tid * 4], xgbase + (size_t)i * G3 + tid * 4);
        asm volatile("cp.async.commit_group;" ::: "memory");
    }
    asm volatile("cp.async.wait_group 2;" ::: "memory");
    __syncthreads();

    for (int t = 0; t < len; t++) {
        const int buf = t & 3;
        float xr = sh_xg[buf][j];
        float xz = sh_xg[buf][64 + j];
        float xn = sh_xg[buf][128 + j];

        const ull* hp = (const ull*)(&sh_h[t & 1][half * 32]);
        ull h8[16];
#pragma unroll
        for (int i = 0; i < 16; i++) h8[i] = hp[i];

        ull a0 = 0ull, a1 = 0ull;
#pragma unroll
        for (int i = 0; i < 16; i += 2) { ffma2(a0, wr[i], h8[i]); ffma2(a1, wr[i + 1], h8[i + 1]); }
        float sr = hsum2(a0) + hsum2(a1);
        sr += __shfl_xor_sync(0xffffffffu, sr, 1);   // issues early; z-fma hides it

        ull c0 = 0ull, c1 = 0ull;
#pragma unroll
        for (int i = 0; i < 16; i += 2) { ffma2(c0, wz[i], h8[i]); ffma2(c1, wz[i + 1], h8[i + 1]); }
        float sz = hsum2(c0) + hsum2(c1);
        sz += __shfl_xor_sync(0xffffffffu, sz, 1);

        float rr = sigmoid_fast(xr + sr + br);       // MUFU.TANH, hides under n-fma

        ull e0 = 0ull, e1 = 0ull;
#pragma unroll
        for (int i = 0; i < 16; i += 2) { ffma2(e0, wn[i], h8[i]); ffma2(e1, wn[i + 1], h8[i + 1]); }
        float sn = hsum2(e0) + hsum2(e1);
        sn += __shfl_xor_sync(0xffffffffu, sn, 1);

        float zz = sigmoid_fast(xz + sz + bz);
        float pre = xn + rr * (sn + bn);
        float nn = tanh_fast(pre);
        myh = nn + zz * (myh - nn);
        if (half == 0) sh_h[(t + 1) & 1][j] = myh;

        // refill: data t+3 into buffer (t+3)&3 (step-(t-1) reads barrier-separated)
        {
            int src = t + 3; if (src > TMAX - 1) src = TMAX - 1;
            if (tid < 48)
                cp_async16(&sh_xg[(t + 3) & 3][tid * 4],
                           xgbase + (size_t)src * G3 + tid * 4);
            asm volatile("cp.async.commit_group;" ::: "memory");
        }
        // my groups for data t+1 done, then barrier -> visible to all. ONE barrier/step.
        asm volatile("cp.async.wait_group 2;" ::: "memory");
        __syncthreads();
    }
    asm volatile("cp.async.wait_group 0;" ::: "memory");

    if (half == 0) g_hT[v * HDIM + j] = myh;
}

// =====================================================================
// Kernel 3a: MLP layer 1 — 64 blocks, one hidden unit each.
// =====================================================================
__global__ __launch_bounds__(128) void mlp1_kernel(
    const float* __restrict__ W1, const float* __restrict__ b1)
{
    const int i = blockIdx.x;
    const int tid = threadIdx.x;
    const int warp = tid >> 5, lane = tid & 31;
    __shared__ float red[4];

    const float* wrow = W1 + (size_t)i * (NV * HDIM);
    float s = 0.f;
#pragma unroll
    for (int it = 0; it < 8; it++) {
        int k = (it * 128 + tid) * 4;
        float4 wv = *(const float4*)(wrow + k);
        float4 hv = *(const float4*)(g_hT + k);
        s += wv.x * hv.x + wv.y * hv.y + wv.z * hv.z + wv.w * hv.w;
    }
#pragma unroll
    for (int off = 16; off; off >>= 1) s += __shfl_xor_sync(0xffffffffu, s, off);
    if (lane == 0) red[warp] = s;
    __syncthreads();
    if (tid == 0)
        g_hid[i] = fmaxf(red[0] + red[1] + red[2] + red[3] + b1[i], 0.f);
}

// =====================================================================
// Kernel 3b: MLP layer 2 — one warp.
// =====================================================================
__global__ __launch_bounds__(32) void mlp2_kernel(
    const float* __restrict__ W2, const float* __restrict__ b2,
    float* __restrict__ out)
{
    const int lane = threadIdx.x;
    float s = g_hid[lane] * W2[lane] + g_hid[lane + 32] * W2[lane + 32];
#pragma unroll
    for (int off = 16; off; off >>= 1) s += __shfl_xor_sync(0xffffffffu, s, off);
    if (lane == 0) out[0] = s + b2[0];
}

// =====================================================================
extern "C" void kernel_launch(void* const* d_in, const int* in_sizes, int n_in,
                              void* d_out, int out_size)
{
    const float* emb     = (const float*)d_in[0];
    const int*   lengths = (const int*)  d_in[1];
    const float* W_ih    = (const float*)d_in[2];
    const float* W_hh    = (const float*)d_in[3];
    const float* b_ih    = (const float*)d_in[4];
    const float* b_hh    = (const float*)d_in[5];
    const float* W1      = (const float*)d_in[6];
    const float* b1      = (const float*)d_in[7];
    const float* W2      = (const float*)d_in[8];
    const float* b2      = (const float*)d_in[9];

    static int smem_set = 0;
    const int GEMM_SMEM = 2 * 32 * 64 * (int)sizeof(float2) + 2 * 32 * 192 * (int)sizeof(float);
    if (!smem_set) {
        cudaFuncSetAttribute(gemm_kernel, cudaFuncAttributeMaxDynamicSharedMemorySize, GEMM_SMEM);
        smem_set = 1;
    }

    transpose_wih<<<(EDIM * G3 + 255) / 256, 256>>>(W_ih);
    dim3 ggrid(TMAX / 64, NV);
    gemm_kernel<<<ggrid, 128, GEMM_SMEM>>>(emb, lengths, b_ih);
    scan_kernel<<<NV, 128>>>(lengths, W_hh, b_hh);
    mlp1_kernel<<<64, 128>>>(W1, b1);
    mlp2_kernel<<<1, 32>>>(W2, b2, (float*)d_out);
}